// round 14
// baseline (speedup 1.0000x reference)
#include <cuda_runtime.h>
#include <math.h>

#define NNODES 20000
#define NEDGES 320000
#define D_IN   256
#define D1     512
#define D2     256
#define D_OUT  64
#define NSTAT  1024   // stats partial blocks
#define NPSUM  128    // colsum partial blocks

// ---------------- scratch (device globals; referenced directly by kernels) --
__device__ int    g_deg[NNODES];
__device__ int    g_rowptr[NNODES + 1];
__device__ int    g_cursor[NNODES];
__device__ int    g_col[NEDGES];
__device__ float  g_agg[NNODES * D1];    // aggregation output / reused as hn2
__device__ float  g_h[NNODES * D1];      // GEMM output
__device__ float  g_hn[NNODES * D1];     // normalized+relu features (layer1)
__device__ float2 g_part[NSTAT];         // stats partials {sum, sumsq}
__device__ float2 g_muinv;               // finalized {mu, 1/(std+eps)}
__device__ float  g_psum[NPSUM * D2];    // column-sum partials

// ---------------- setup: zero per-replay state ------------------------------
__global__ void zero_k() {
    int i = blockIdx.x * blockDim.x + threadIdx.x;
    if (i < NNODES) { g_deg[i] = 0; g_cursor[i] = 0; }
}

// ---------------- CSR build (edge_index is INT32: [2, E] row-major) ---------
__global__ void hist_k(const int* __restrict__ ei) {
    int i = blockIdx.x * blockDim.x + threadIdx.x;
    if (i < NEDGES) {
        int d = ei[NEDGES + i];
        if ((unsigned)d < (unsigned)NNODES) atomicAdd(&g_deg[d], 1);
    }
}

__global__ void scan_k() {  // single-block exclusive scan over g_deg
    __shared__ int sh[1024];
    __shared__ int carry;
    if (threadIdx.x == 0) carry = 0;
    __syncthreads();
    for (int base = 0; base < NNODES; base += 1024) {
        int i = base + (int)threadIdx.x;
        int v = (i < NNODES) ? g_deg[i] : 0;
        sh[threadIdx.x] = v;
        __syncthreads();
        for (int off = 1; off < 1024; off <<= 1) {
            int t = (threadIdx.x >= (unsigned)off) ? sh[threadIdx.x - off] : 0;
            __syncthreads();
            sh[threadIdx.x] += t;
            __syncthreads();
        }
        if (i < NNODES) g_rowptr[i] = carry + sh[threadIdx.x] - v;
        __syncthreads();
        if (threadIdx.x == 0) carry += sh[1023];
        __syncthreads();
    }
    if (threadIdx.x == 0) g_rowptr[NNODES] = carry;
}

__global__ void scatter_k(const int* __restrict__ ei) {
    int i = blockIdx.x * blockDim.x + threadIdx.x;
    if (i < NEDGES) {
        int s = ei[i];
        int d = ei[NEDGES + i];
        if ((unsigned)s < (unsigned)NNODES && (unsigned)d < (unsigned)NNODES) {
            int pos = atomicAdd(&g_cursor[d], 1);
            g_col[g_rowptr[d] + pos] = s;
        }
    }
}

// ---------------- softmax aggregation (online, one pass) --------------------
// Fx == nullptr -> read features from g_hn. Output always g_agg.
template <int D>
__global__ void agg_k(const float* __restrict__ Fx, const float* __restrict__ t) {
    const float* F = Fx ? Fx : (const float*)g_hn;
    int row = blockIdx.x;
    int c   = threadIdx.x;
    int s0 = g_rowptr[row], s1 = g_rowptr[row + 1];
    float tc  = t[c];
    float mx  = -3.0e38f, den = 0.f, num = 0.f;
    for (int e = s0; e < s1; e++) {
        int   s = g_col[e];
        float m = F[(size_t)s * D + c];
        float a = m * tc;
        if (a > mx) {
            float r = __expf(mx - a);
            den *= r; num *= r; mx = a;
        }
        float w = __expf(a - mx);
        den += w;
        num += m * w;
    }
    g_agg[(size_t)row * D + c] = (s1 > s0) ? (num / den) : 0.f;
}

// ---------------- fused dual GEMM: g_h = g_agg@W1 + A2@W2 + bias ------------
// A2x == nullptr -> A2 = g_hn. 128x128 tile, BK=8, 256 threads, 8x8/thread.
__global__ void __launch_bounds__(256, 2) gemm_dual_k(
    const float* __restrict__ A2x, const float* __restrict__ W1,
    const float* __restrict__ W2, const float* __restrict__ bias,
    int K, int M, int Nn)
{
    __shared__ float As[8][132];
    __shared__ float Bs[8][132];
    const float* A2 = A2x ? A2x : (const float*)g_hn;
    const int tid     = threadIdx.x;
    const int rowBase = blockIdx.y * 128;
    const int colBase = blockIdx.x * 128;
    const int aRow = tid >> 1;
    const int aCol = (tid & 1) << 2;
    const int bRow = tid >> 5;
    const int bCol = (tid & 31) << 2;
    const int ty = tid >> 4;
    const int tx = tid & 15;

    float acc[8][8];
#pragma unroll
    for (int i = 0; i < 8; i++)
#pragma unroll
        for (int j = 0; j < 8; j++) acc[i][j] = 0.f;

    for (int part = 0; part < 2; part++) {
        const float* A = part ? A2 : (const float*)g_agg;
        const float* W = part ? W2 : W1;
        for (int k0 = 0; k0 < K; k0 += 8) {
            float4 av = make_float4(0.f, 0.f, 0.f, 0.f);
            int ar = rowBase + aRow;
            if (ar < M)
                av = *reinterpret_cast<const float4*>(&A[(size_t)ar * K + k0 + aCol]);
            As[aCol + 0][aRow] = av.x;
            As[aCol + 1][aRow] = av.y;
            As[aCol + 2][aRow] = av.z;
            As[aCol + 3][aRow] = av.w;
            *reinterpret_cast<float4*>(&Bs[bRow][bCol]) =
                *reinterpret_cast<const float4*>(&W[(size_t)(k0 + bRow) * Nn + colBase + bCol]);
            __syncthreads();
#pragma unroll
            for (int k = 0; k < 8; k++) {
                float a[8], b[8];
                *reinterpret_cast<float4*>(a)     = *reinterpret_cast<float4*>(&As[k][ty * 8]);
                *reinterpret_cast<float4*>(a + 4) = *reinterpret_cast<float4*>(&As[k][ty * 8 + 4]);
                *reinterpret_cast<float4*>(b)     = *reinterpret_cast<float4*>(&Bs[k][tx * 8]);
                *reinterpret_cast<float4*>(b + 4) = *reinterpret_cast<float4*>(&Bs[k][tx * 8 + 4]);
#pragma unroll
                for (int i = 0; i < 8; i++)
#pragma unroll
                    for (int j = 0; j < 8; j++) acc[i][j] += a[i] * b[j];
            }
            __syncthreads();
        }
    }

#pragma unroll
    for (int i = 0; i < 8; i++) {
        int r = rowBase + ty * 8 + i;
        if (r < M) {
            int cc = colBase + tx * 8;
#pragma unroll
            for (int j = 0; j < 8; j++)
                g_h[(size_t)r * Nn + cc + j] = acc[i][j] + bias[cc + j];
        }
    }
}

// ---------------- graph-LN statistics (2-stage, no 64-bit atomics) ----------
__global__ void stats_k(size_t n) {  // grid = NSTAT blocks, 256 threads
    float s = 0.f, ss = 0.f;
    for (size_t i = (size_t)blockIdx.x * blockDim.x + threadIdx.x; i < n;
         i += (size_t)gridDim.x * blockDim.x) {
        float v = g_h[i];
        s += v;
        ss += v * v;
    }
    for (int o = 16; o; o >>= 1) {
        s  += __shfl_down_sync(0xffffffffu, s, o);
        ss += __shfl_down_sync(0xffffffffu, ss, o);
    }
    __shared__ float ws[2][8];
    int w = threadIdx.x >> 5, l = threadIdx.x & 31;
    if (l == 0) { ws[0][w] = s; ws[1][w] = ss; }
    __syncthreads();
    if (threadIdx.x == 0) {
        float ts = 0.f, tss = 0.f;
        for (int i = 0; i < 8; i++) { ts += ws[0][i]; tss += ws[1][i]; }
        g_part[blockIdx.x] = make_float2(ts, tss);
    }
}

__global__ void fin_k(size_t n) {  // single block, 1024 threads
    __shared__ double ds[1024], dss[1024];
    float2 p = g_part[threadIdx.x];
    ds[threadIdx.x]  = (double)p.x;
    dss[threadIdx.x] = (double)p.y;
    __syncthreads();
    for (int o = 512; o; o >>= 1) {
        if ((int)threadIdx.x < o) {
            ds[threadIdx.x]  += ds[threadIdx.x + o];
            dss[threadIdx.x] += dss[threadIdx.x + o];
        }
        __syncthreads();
    }
    if (threadIdx.x == 0) {
        double mu  = ds[0] / (double)n;
        double var = dss[0] / (double)n - mu * mu;
        if (var < 0.0) var = 0.0;
        double inv = 1.0 / (sqrt(var) + 1e-5);  // graph-LN: (x-mu)/(std+eps)
        g_muinv = make_float2((float)mu, (float)inv);
    }
}

// layer==1 -> out g_hn ; layer==2 -> out g_agg (reused)
__global__ void lnrelu_k(const float* __restrict__ g, const float* __restrict__ b,
                         int layer, int Dmask, size_t n) {
    float* out = (layer == 1) ? g_hn : g_agg;
    float2 mi = g_muinv;
    for (size_t i = (size_t)blockIdx.x * blockDim.x + threadIdx.x; i < n;
         i += (size_t)gridDim.x * blockDim.x) {
        int   c = (int)(i & (size_t)Dmask);
        float y = (g_h[i] - mi.x) * mi.y * g[c] + b[c];
        out[i] = fmaxf(y, 0.f);
    }
}

// ---------------- pooling + head (deterministic, no atomics) ----------------
__global__ void colsum_k() {  // grid = NPSUM blocks x 256 threads, reads g_agg
    int c = threadIdx.x;
    float s = 0.f;
    for (int r = blockIdx.x; r < NNODES; r += gridDim.x)
        s += g_agg[(size_t)r * D2 + c];
    g_psum[blockIdx.x * D2 + c] = s;
}

__global__ void final_k(const float* __restrict__ Wf, const float* __restrict__ bf,
                        const float* __restrict__ gx, const float* __restrict__ bx,
                        float* __restrict__ out) {
    __shared__ float shp[D2];
    __shared__ float shv[D_OUT];
    __shared__ float smu, sinv;
    int tid = threadIdx.x;  // 256
    float s = 0.f;
    for (int p = 0; p < NPSUM; p++) s += g_psum[p * D2 + tid];
    shp[tid] = s * (1.f / (float)NNODES);
    __syncthreads();
    if (tid < D_OUT) {
        float v = 0.f;
        for (int k = 0; k < D2; k++) v += shp[k] * Wf[k * D_OUT + tid];
        shv[tid] = v + bf[tid];
    }
    __syncthreads();
    if (tid == 0) {
        float m = 0.f;
        for (int k = 0; k < D_OUT; k++) m += shv[k];
        m /= (float)D_OUT;
        float va = 0.f;
        for (int k = 0; k < D_OUT; k++) { float d = shv[k] - m; va += d * d; }
        va /= (float)D_OUT;
        smu  = m;
        sinv = 1.f / sqrtf(va + 1e-5f);  // final LN: /sqrt(var+eps)
    }
    __syncthreads();
    if (tid < D_OUT) {
        float y = (shv[tid] - smu) * sinv * gx[tid] + bx[tid];
        out[tid] = fmaxf(y, 0.f);
    }
}

// ---------------- launch ------------------------------------------------------
extern "C" void kernel_launch(void* const* d_in, const int* in_sizes, int n_in,
                              void* d_out, int out_size) {
    const float* x   = (const float*)d_in[0];
    const int*   ei  = (const int*)d_in[1];     // int32! (JAX x64 disabled)
    const float* t1  = (const float*)d_in[2];
    const float* Wl1 = (const float*)d_in[3];
    const float* bl1 = (const float*)d_in[4];
    const float* Wr1 = (const float*)d_in[5];
    const float* g1  = (const float*)d_in[6];
    const float* be1 = (const float*)d_in[7];
    const float* t2  = (const float*)d_in[8];
    const float* Wl2 = (const float*)d_in[9];
    const float* bl2 = (const float*)d_in[10];
    const float* Wr2 = (const float*)d_in[11];
    const float* g2  = (const float*)d_in[12];
    const float* be2 = (const float*)d_in[13];
    const float* Wf  = (const float*)d_in[14];
    const float* bf  = (const float*)d_in[15];
    const float* gx  = (const float*)d_in[16];
    const float* bx  = (const float*)d_in[17];
    float*       out = (float*)d_out;

    zero_k<<<(NNODES + 255) / 256, 256>>>();
    hist_k<<<(NEDGES + 255) / 256, 256>>>(ei);
    scan_k<<<1, 1024>>>();
    scatter_k<<<(NEDGES + 255) / 256, 256>>>(ei);

    // ---- layer 1 ----
    agg_k<D_IN><<<NNODES, D_IN>>>(x, t1);
    gemm_dual_k<<<dim3(D1 / 128, (NNODES + 127) / 128), 256>>>(
        x, Wl1, Wr1, bl1, D_IN, NNODES, D1);
    stats_k<<<NSTAT, 256>>>((size_t)NNODES * D1);
    fin_k<<<1, 1024>>>((size_t)NNODES * D1);
    lnrelu_k<<<2048, 256>>>(g1, be1, 1, D1 - 1, (size_t)NNODES * D1);

    // ---- layer 2 ----
    agg_k<D1><<<NNODES, D1>>>(nullptr, t2);
    gemm_dual_k<<<dim3(D2 / 128, (NNODES + 127) / 128), 256>>>(
        nullptr, Wl2, Wr2, bl2, D1, NNODES, D2);
    stats_k<<<NSTAT, 256>>>((size_t)NNODES * D2);
    fin_k<<<1, 1024>>>((size_t)NNODES * D2);
    lnrelu_k<<<2048, 256>>>(g2, be2, 2, D2 - 1, (size_t)NNODES * D2);

    // ---- head ----
    colsum_k<<<NPSUM, 256>>>();
    final_k<<<1, D2>>>(Wf, bf, gx, bx, out);
}

// round 15
// speedup vs baseline: 1.0027x; 1.0027x over previous
#include <cuda_runtime.h>
#include <math.h>

#define NNODES 20000
#define NEDGES 320000
#define D_IN   256
#define D1     512
#define D2     256
#define D_OUT  64
#define NSTAT  1024   // stats partial blocks
#define NPSUM  128    // colsum partial blocks

// ---------------- scratch (device globals; referenced directly by kernels) --
__device__ int    g_deg[NNODES];
__device__ int    g_rowptr[NNODES + 1];
__device__ int    g_cursor[NNODES];
__device__ int    g_col[NEDGES];
__device__ float  g_agg[NNODES * D1];    // aggregation output / reused as hn2
__device__ float  g_h[NNODES * D1];      // GEMM output
__device__ float  g_hn[NNODES * D1];     // normalized+relu features (layer1)
__device__ float2 g_part[NSTAT];         // stats partials {sum, sumsq}
__device__ float2 g_muinv;               // finalized {mu, 1/(std+eps)}
__device__ float  g_psum[NPSUM * D2];    // column-sum partials

// ---------------- setup: zero per-replay state ------------------------------
__global__ void zero_k() {
    int i = blockIdx.x * blockDim.x + threadIdx.x;
    if (i < NNODES) { g_deg[i] = 0; g_cursor[i] = 0; }
}

// ---------------- CSR build (edge_index is INT32: [2, E] row-major) ---------
__global__ void hist_k(const int* __restrict__ ei) {
    int i = blockIdx.x * blockDim.x + threadIdx.x;
    if (i < NEDGES) {
        int d = ei[NEDGES + i];
        if ((unsigned)d < (unsigned)NNODES) atomicAdd(&g_deg[d], 1);
    }
}

__global__ void scan_k() {  // single-block exclusive scan over g_deg
    __shared__ int sh[1024];
    __shared__ int carry;
    if (threadIdx.x == 0) carry = 0;
    __syncthreads();
    for (int base = 0; base < NNODES; base += 1024) {
        int i = base + (int)threadIdx.x;
        int v = (i < NNODES) ? g_deg[i] : 0;
        sh[threadIdx.x] = v;
        __syncthreads();
        for (int off = 1; off < 1024; off <<= 1) {
            int t = (threadIdx.x >= (unsigned)off) ? sh[threadIdx.x - off] : 0;
            __syncthreads();
            sh[threadIdx.x] += t;
            __syncthreads();
        }
        if (i < NNODES) g_rowptr[i] = carry + sh[threadIdx.x] - v;
        __syncthreads();
        if (threadIdx.x == 0) carry += sh[1023];
        __syncthreads();
    }
    if (threadIdx.x == 0) g_rowptr[NNODES] = carry;
}

__global__ void scatter_k(const int* __restrict__ ei) {
    int i = blockIdx.x * blockDim.x + threadIdx.x;
    if (i < NEDGES) {
        int s = ei[i];
        int d = ei[NEDGES + i];
        if ((unsigned)s < (unsigned)NNODES && (unsigned)d < (unsigned)NNODES) {
            int pos = atomicAdd(&g_cursor[d], 1);
            g_col[g_rowptr[d] + pos] = s;
        }
    }
}

// ---------------- softmax aggregation (online, one pass) --------------------
// Fx == nullptr -> read features from g_hn. Output always g_agg.
template <int D>
__global__ void agg_k(const float* __restrict__ Fx, const float* __restrict__ t) {
    const float* F = Fx ? Fx : (const float*)g_hn;
    int row = blockIdx.x;
    int c   = threadIdx.x;
    int s0 = g_rowptr[row], s1 = g_rowptr[row + 1];
    float tc  = t[c];
    float mx  = -3.0e38f, den = 0.f, num = 0.f;
    for (int e = s0; e < s1; e++) {
        int   s = g_col[e];
        float m = F[(size_t)s * D + c];
        float a = m * tc;
        if (a > mx) {
            float r = __expf(mx - a);
            den *= r; num *= r; mx = a;
        }
        float w = __expf(a - mx);
        den += w;
        num += m * w;
    }
    g_agg[(size_t)row * D + c] = (s1 > s0) ? (num / den) : 0.f;
}

// ---------------- fused dual GEMM: g_h = g_agg@W1 + A2@W2 + bias ------------
// A2x == nullptr -> A2 = g_hn. 128x128 tile, BK=8, 256 threads, 8x8/thread.
__global__ void __launch_bounds__(256, 2) gemm_dual_k(
    const float* __restrict__ A2x, const float* __restrict__ W1,
    const float* __restrict__ W2, const float* __restrict__ bias,
    int K, int M, int Nn)
{
    __shared__ float As[8][132];
    __shared__ float Bs[8][132];
    const float* A2 = A2x ? A2x : (const float*)g_hn;
    const int tid     = threadIdx.x;
    const int rowBase = blockIdx.y * 128;
    const int colBase = blockIdx.x * 128;
    const int aRow = tid >> 1;
    const int aCol = (tid & 1) << 2;
    const int bRow = tid >> 5;
    const int bCol = (tid & 31) << 2;
    const int ty = tid >> 4;
    const int tx = tid & 15;

    float acc[8][8];
#pragma unroll
    for (int i = 0; i < 8; i++)
#pragma unroll
        for (int j = 0; j < 8; j++) acc[i][j] = 0.f;

    for (int part = 0; part < 2; part++) {
        const float* A = part ? A2 : (const float*)g_agg;
        const float* W = part ? W2 : W1;
        for (int k0 = 0; k0 < K; k0 += 8) {
            float4 av = make_float4(0.f, 0.f, 0.f, 0.f);
            int ar = rowBase + aRow;
            if (ar < M)
                av = *reinterpret_cast<const float4*>(&A[(size_t)ar * K + k0 + aCol]);
            As[aCol + 0][aRow] = av.x;
            As[aCol + 1][aRow] = av.y;
            As[aCol + 2][aRow] = av.z;
            As[aCol + 3][aRow] = av.w;
            *reinterpret_cast<float4*>(&Bs[bRow][bCol]) =
                *reinterpret_cast<const float4*>(&W[(size_t)(k0 + bRow) * Nn + colBase + bCol]);
            __syncthreads();
#pragma unroll
            for (int k = 0; k < 8; k++) {
                float a[8], b[8];
                *reinterpret_cast<float4*>(a)     = *reinterpret_cast<float4*>(&As[k][ty * 8]);
                *reinterpret_cast<float4*>(a + 4) = *reinterpret_cast<float4*>(&As[k][ty * 8 + 4]);
                *reinterpret_cast<float4*>(b)     = *reinterpret_cast<float4*>(&Bs[k][tx * 8]);
                *reinterpret_cast<float4*>(b + 4) = *reinterpret_cast<float4*>(&Bs[k][tx * 8 + 4]);
#pragma unroll
                for (int i = 0; i < 8; i++)
#pragma unroll
                    for (int j = 0; j < 8; j++) acc[i][j] += a[i] * b[j];
            }
            __syncthreads();
        }
    }

#pragma unroll
    for (int i = 0; i < 8; i++) {
        int r = rowBase + ty * 8 + i;
        if (r < M) {
            int cc = colBase + tx * 8;
#pragma unroll
            for (int j = 0; j < 8; j++)
                g_h[(size_t)r * Nn + cc + j] = acc[i][j] + bias[cc + j];
        }
    }
}

// ---------------- graph-LN statistics (2-stage, no 64-bit atomics) ----------
__global__ void stats_k(size_t n) {  // grid = NSTAT blocks, 256 threads
    float s = 0.f, ss = 0.f;
    for (size_t i = (size_t)blockIdx.x * blockDim.x + threadIdx.x; i < n;
         i += (size_t)gridDim.x * blockDim.x) {
        float v = g_h[i];
        s += v;
        ss += v * v;
    }
    for (int o = 16; o; o >>= 1) {
        s  += __shfl_down_sync(0xffffffffu, s, o);
        ss += __shfl_down_sync(0xffffffffu, ss, o);
    }
    __shared__ float ws[2][8];
    int w = threadIdx.x >> 5, l = threadIdx.x & 31;
    if (l == 0) { ws[0][w] = s; ws[1][w] = ss; }
    __syncthreads();
    if (threadIdx.x == 0) {
        float ts = 0.f, tss = 0.f;
        for (int i = 0; i < 8; i++) { ts += ws[0][i]; tss += ws[1][i]; }
        g_part[blockIdx.x] = make_float2(ts, tss);
    }
}

__global__ void fin_k(size_t n) {  // single block, 1024 threads
    __shared__ double ds[1024], dss[1024];
    float2 p = g_part[threadIdx.x];
    ds[threadIdx.x]  = (double)p.x;
    dss[threadIdx.x] = (double)p.y;
    __syncthreads();
    for (int o = 512; o; o >>= 1) {
        if ((int)threadIdx.x < o) {
            ds[threadIdx.x]  += ds[threadIdx.x + o];
            dss[threadIdx.x] += dss[threadIdx.x + o];
        }
        __syncthreads();
    }
    if (threadIdx.x == 0) {
        double mu  = ds[0] / (double)n;
        double var = dss[0] / (double)n - mu * mu;
        if (var < 0.0) var = 0.0;
        double inv = 1.0 / (sqrt(var) + 1e-5);  // graph-LN: (x-mu)/(std+eps)
        g_muinv = make_float2((float)mu, (float)inv);
    }
}

// layer==1 -> out g_hn ; layer==2 -> out g_agg (reused)
__global__ void lnrelu_k(const float* __restrict__ g, const float* __restrict__ b,
                         int layer, int Dmask, size_t n) {
    float* out = (layer == 1) ? g_hn : g_agg;
    float2 mi = g_muinv;
    for (size_t i = (size_t)blockIdx.x * blockDim.x + threadIdx.x; i < n;
         i += (size_t)gridDim.x * blockDim.x) {
        int   c = (int)(i & (size_t)Dmask);
        float y = (g_h[i] - mi.x) * mi.y * g[c] + b[c];
        out[i] = fmaxf(y, 0.f);
    }
}

// ---------------- pooling + head (deterministic, no atomics) ----------------
__global__ void colsum_k() {  // grid = NPSUM blocks x 256 threads, reads g_agg
    int c = threadIdx.x;
    float s = 0.f;
    for (int r = blockIdx.x; r < NNODES; r += gridDim.x)
        s += g_agg[(size_t)r * D2 + c];
    g_psum[blockIdx.x * D2 + c] = s;
}

__global__ void final_k(const float* __restrict__ Wf, const float* __restrict__ bf,
                        const float* __restrict__ gx, const float* __restrict__ bx,
                        float* __restrict__ out) {
    __shared__ float shp[D2];
    __shared__ float shv[D_OUT];
    __shared__ float smu, sinv;
    int tid = threadIdx.x;  // 256
    float s = 0.f;
    for (int p = 0; p < NPSUM; p++) s += g_psum[p * D2 + tid];
    shp[tid] = s * (1.f / (float)NNODES);
    __syncthreads();
    if (tid < D_OUT) {
        float v = 0.f;
        for (int k = 0; k < D2; k++) v += shp[k] * Wf[k * D_OUT + tid];
        shv[tid] = v + bf[tid];
    }
    __syncthreads();
    if (tid == 0) {
        float m = 0.f;
        for (int k = 0; k < D_OUT; k++) m += shv[k];
        m /= (float)D_OUT;
        float va = 0.f;
        for (int k = 0; k < D_OUT; k++) { float d = shv[k] - m; va += d * d; }
        va /= (float)D_OUT;
        smu  = m;
        sinv = 1.f / sqrtf(va + 1e-5f);  // final LN: /sqrt(var+eps)
    }
    __syncthreads();
    if (tid < D_OUT) {
        float y = (shv[tid] - smu) * sinv * gx[tid] + bx[tid];
        out[tid] = fmaxf(y, 0.f);
    }
}

// ---------------- launch ------------------------------------------------------
extern "C" void kernel_launch(void* const* d_in, const int* in_sizes, int n_in,
                              void* d_out, int out_size) {
    const float* x   = (const float*)d_in[0];
    const int*   ei  = (const int*)d_in[1];     // int32! (JAX x64 disabled)
    const float* t1  = (const float*)d_in[2];
    const float* Wl1 = (const float*)d_in[3];
    const float* bl1 = (const float*)d_in[4];
    const float* Wr1 = (const float*)d_in[5];
    const float* g1  = (const float*)d_in[6];
    const float* be1 = (const float*)d_in[7];
    const float* t2  = (const float*)d_in[8];
    const float* Wl2 = (const float*)d_in[9];
    const float* bl2 = (const float*)d_in[10];
    const float* Wr2 = (const float*)d_in[11];
    const float* g2  = (const float*)d_in[12];
    const float* be2 = (const float*)d_in[13];
    const float* Wf  = (const float*)d_in[14];
    const float* bf  = (const float*)d_in[15];
    const float* gx  = (const float*)d_in[16];
    const float* bx  = (const float*)d_in[17];
    float*       out = (float*)d_out;

    zero_k<<<(NNODES + 255) / 256, 256>>>();
    hist_k<<<(NEDGES + 255) / 256, 256>>>(ei);
    scan_k<<<1, 1024>>>();
    scatter_k<<<(NEDGES + 255) / 256, 256>>>(ei);

    // ---- layer 1 ----
    agg_k<D_IN><<<NNODES, D_IN>>>(x, t1);
    gemm_dual_k<<<dim3(D1 / 128, (NNODES + 127) / 128), 256>>>(
        x, Wl1, Wr1, bl1, D_IN, NNODES, D1);
    stats_k<<<NSTAT, 256>>>((size_t)NNODES * D1);
    fin_k<<<1, 1024>>>((size_t)NNODES * D1);
    lnrelu_k<<<2048, 256>>>(g1, be1, 1, D1 - 1, (size_t)NNODES * D1);

    // ---- layer 2 ----
    agg_k<D1><<<NNODES, D1>>>(nullptr, t2);
    gemm_dual_k<<<dim3(D2 / 128, (NNODES + 127) / 128), 256>>>(
        nullptr, Wl2, Wr2, bl2, D1, NNODES, D2);
    stats_k<<<NSTAT, 256>>>((size_t)NNODES * D2);
    fin_k<<<1, 1024>>>((size_t)NNODES * D2);
    lnrelu_k<<<2048, 256>>>(g2, be2, 2, D2 - 1, (size_t)NNODES * D2);

    // ---- head ----
    colsum_k<<<NPSUM, 256>>>();
    final_k<<<1, D2>>>(Wf, bf, gx, bx, out);
}

// round 16
// speedup vs baseline: 1.0044x; 1.0017x over previous
#include <cuda_runtime.h>
#include <math.h>

#define NNODES 20000
#define NEDGES 320000
#define D_IN   256
#define D1     512
#define D2     256
#define D_OUT  64
#define NSTAT  1024   // stats partial blocks
#define NPSUM  128    // colsum partial blocks

// ---------------- scratch (device globals; referenced directly by kernels) --
__device__ int    g_deg[NNODES];
__device__ int    g_rowptr[NNODES + 1];
__device__ int    g_cursor[NNODES];
__device__ int    g_col[NEDGES];
__device__ float  g_agg[NNODES * D1];    // aggregation output / reused as hn2
__device__ float  g_h[NNODES * D1];      // GEMM output
__device__ float  g_hn[NNODES * D1];     // normalized+relu features (layer1)
__device__ float2 g_part[NSTAT];         // stats partials {sum, sumsq}
__device__ float2 g_muinv;               // finalized {mu, 1/(std+eps)}
__device__ float  g_psum[NPSUM * D2];    // column-sum partials

// ---------------- setup: zero per-replay state ------------------------------
__global__ void zero_k() {
    int i = blockIdx.x * blockDim.x + threadIdx.x;
    if (i < NNODES) { g_deg[i] = 0; g_cursor[i] = 0; }
}

// ---------------- CSR build (edge_index is INT32: [2, E] row-major) ---------
__global__ void hist_k(const int* __restrict__ ei) {
    int i = blockIdx.x * blockDim.x + threadIdx.x;
    if (i < NEDGES) {
        int d = ei[NEDGES + i];
        if ((unsigned)d < (unsigned)NNODES) atomicAdd(&g_deg[d], 1);
    }
}

__global__ void scan_k() {  // single-block exclusive scan over g_deg
    __shared__ int sh[1024];
    __shared__ int carry;
    if (threadIdx.x == 0) carry = 0;
    __syncthreads();
    for (int base = 0; base < NNODES; base += 1024) {
        int i = base + (int)threadIdx.x;
        int v = (i < NNODES) ? g_deg[i] : 0;
        sh[threadIdx.x] = v;
        __syncthreads();
        for (int off = 1; off < 1024; off <<= 1) {
            int t = (threadIdx.x >= (unsigned)off) ? sh[threadIdx.x - off] : 0;
            __syncthreads();
            sh[threadIdx.x] += t;
            __syncthreads();
        }
        if (i < NNODES) g_rowptr[i] = carry + sh[threadIdx.x] - v;
        __syncthreads();
        if (threadIdx.x == 0) carry += sh[1023];
        __syncthreads();
    }
    if (threadIdx.x == 0) g_rowptr[NNODES] = carry;
}

__global__ void scatter_k(const int* __restrict__ ei) {
    int i = blockIdx.x * blockDim.x + threadIdx.x;
    if (i < NEDGES) {
        int s = ei[i];
        int d = ei[NEDGES + i];
        if ((unsigned)s < (unsigned)NNODES && (unsigned)d < (unsigned)NNODES) {
            int pos = atomicAdd(&g_cursor[d], 1);
            g_col[g_rowptr[d] + pos] = s;
        }
    }
}

// ---------------- softmax aggregation (online, one pass) --------------------
// Fx == nullptr -> read features from g_hn. Output always g_agg.
template <int D>
__global__ void agg_k(const float* __restrict__ Fx, const float* __restrict__ t) {
    const float* F = Fx ? Fx : (const float*)g_hn;
    int row = blockIdx.x;
    int c   = threadIdx.x;
    int s0 = g_rowptr[row], s1 = g_rowptr[row + 1];
    float tc  = t[c];
    float mx  = -3.0e38f, den = 0.f, num = 0.f;
    for (int e = s0; e < s1; e++) {
        int   s = g_col[e];
        float m = F[(size_t)s * D + c];
        float a = m * tc;
        if (a > mx) {
            float r = __expf(mx - a);
            den *= r; num *= r; mx = a;
        }
        float w = __expf(a - mx);
        den += w;
        num += m * w;
    }
    g_agg[(size_t)row * D + c] = (s1 > s0) ? (num / den) : 0.f;
}

// ---------------- fused dual GEMM: g_h = g_agg@W1 + A2@W2 + bias ------------
// A2x == nullptr -> A2 = g_hn. 128x128 tile, BK=8, 256 threads, 8x8/thread.
__global__ void __launch_bounds__(256, 2) gemm_dual_k(
    const float* __restrict__ A2x, const float* __restrict__ W1,
    const float* __restrict__ W2, const float* __restrict__ bias,
    int K, int M, int Nn)
{
    __shared__ float As[8][132];
    __shared__ float Bs[8][132];
    const float* A2 = A2x ? A2x : (const float*)g_hn;
    const int tid     = threadIdx.x;
    const int rowBase = blockIdx.y * 128;
    const int colBase = blockIdx.x * 128;
    const int aRow = tid >> 1;
    const int aCol = (tid & 1) << 2;
    const int bRow = tid >> 5;
    const int bCol = (tid & 31) << 2;
    const int ty = tid >> 4;
    const int tx = tid & 15;

    float acc[8][8];
#pragma unroll
    for (int i = 0; i < 8; i++)
#pragma unroll
        for (int j = 0; j < 8; j++) acc[i][j] = 0.f;

    for (int part = 0; part < 2; part++) {
        const float* A = part ? A2 : (const float*)g_agg;
        const float* W = part ? W2 : W1;
        for (int k0 = 0; k0 < K; k0 += 8) {
            float4 av = make_float4(0.f, 0.f, 0.f, 0.f);
            int ar = rowBase + aRow;
            if (ar < M)
                av = *reinterpret_cast<const float4*>(&A[(size_t)ar * K + k0 + aCol]);
            As[aCol + 0][aRow] = av.x;
            As[aCol + 1][aRow] = av.y;
            As[aCol + 2][aRow] = av.z;
            As[aCol + 3][aRow] = av.w;
            *reinterpret_cast<float4*>(&Bs[bRow][bCol]) =
                *reinterpret_cast<const float4*>(&W[(size_t)(k0 + bRow) * Nn + colBase + bCol]);
            __syncthreads();
#pragma unroll
            for (int k = 0; k < 8; k++) {
                float a[8], b[8];
                *reinterpret_cast<float4*>(a)     = *reinterpret_cast<float4*>(&As[k][ty * 8]);
                *reinterpret_cast<float4*>(a + 4) = *reinterpret_cast<float4*>(&As[k][ty * 8 + 4]);
                *reinterpret_cast<float4*>(b)     = *reinterpret_cast<float4*>(&Bs[k][tx * 8]);
                *reinterpret_cast<float4*>(b + 4) = *reinterpret_cast<float4*>(&Bs[k][tx * 8 + 4]);
#pragma unroll
                for (int i = 0; i < 8; i++)
#pragma unroll
                    for (int j = 0; j < 8; j++) acc[i][j] += a[i] * b[j];
            }
            __syncthreads();
        }
    }

#pragma unroll
    for (int i = 0; i < 8; i++) {
        int r = rowBase + ty * 8 + i;
        if (r < M) {
            int cc = colBase + tx * 8;
#pragma unroll
            for (int j = 0; j < 8; j++)
                g_h[(size_t)r * Nn + cc + j] = acc[i][j] + bias[cc + j];
        }
    }
}

// ---------------- graph-LN statistics (2-stage, no 64-bit atomics) ----------
__global__ void stats_k(size_t n) {  // grid = NSTAT blocks, 256 threads
    float s = 0.f, ss = 0.f;
    for (size_t i = (size_t)blockIdx.x * blockDim.x + threadIdx.x; i < n;
         i += (size_t)gridDim.x * blockDim.x) {
        float v = g_h[i];
        s += v;
        ss += v * v;
    }
    for (int o = 16; o; o >>= 1) {
        s  += __shfl_down_sync(0xffffffffu, s, o);
        ss += __shfl_down_sync(0xffffffffu, ss, o);
    }
    __shared__ float ws[2][8];
    int w = threadIdx.x >> 5, l = threadIdx.x & 31;
    if (l == 0) { ws[0][w] = s; ws[1][w] = ss; }
    __syncthreads();
    if (threadIdx.x == 0) {
        float ts = 0.f, tss = 0.f;
        for (int i = 0; i < 8; i++) { ts += ws[0][i]; tss += ws[1][i]; }
        g_part[blockIdx.x] = make_float2(ts, tss);
    }
}

__global__ void fin_k(size_t n) {  // single block, 1024 threads
    __shared__ double ds[1024], dss[1024];
    float2 p = g_part[threadIdx.x];
    ds[threadIdx.x]  = (double)p.x;
    dss[threadIdx.x] = (double)p.y;
    __syncthreads();
    for (int o = 512; o; o >>= 1) {
        if ((int)threadIdx.x < o) {
            ds[threadIdx.x]  += ds[threadIdx.x + o];
            dss[threadIdx.x] += dss[threadIdx.x + o];
        }
        __syncthreads();
    }
    if (threadIdx.x == 0) {
        double mu  = ds[0] / (double)n;
        double var = dss[0] / (double)n - mu * mu;
        if (var < 0.0) var = 0.0;
        double inv = 1.0 / (sqrt(var) + 1e-5);  // graph-LN: (x-mu)/(std+eps)
        g_muinv = make_float2((float)mu, (float)inv);
    }
}

// layer==1 -> out g_hn ; layer==2 -> out g_agg (reused)
__global__ void lnrelu_k(const float* __restrict__ g, const float* __restrict__ b,
                         int layer, int Dmask, size_t n) {
    float* out = (layer == 1) ? g_hn : g_agg;
    float2 mi = g_muinv;
    for (size_t i = (size_t)blockIdx.x * blockDim.x + threadIdx.x; i < n;
         i += (size_t)gridDim.x * blockDim.x) {
        int   c = (int)(i & (size_t)Dmask);
        float y = (g_h[i] - mi.x) * mi.y * g[c] + b[c];
        out[i] = fmaxf(y, 0.f);
    }
}

// ---------------- pooling + head (deterministic, no atomics) ----------------
__global__ void colsum_k() {  // grid = NPSUM blocks x 256 threads, reads g_agg
    int c = threadIdx.x;
    float s = 0.f;
    for (int r = blockIdx.x; r < NNODES; r += gridDim.x)
        s += g_agg[(size_t)r * D2 + c];
    g_psum[blockIdx.x * D2 + c] = s;
}

__global__ void final_k(const float* __restrict__ Wf, const float* __restrict__ bf,
                        const float* __restrict__ gx, const float* __restrict__ bx,
                        float* __restrict__ out) {
    __shared__ float shp[D2];
    __shared__ float shv[D_OUT];
    __shared__ float smu, sinv;
    int tid = threadIdx.x;  // 256
    float s = 0.f;
    for (int p = 0; p < NPSUM; p++) s += g_psum[p * D2 + tid];
    shp[tid] = s * (1.f / (float)NNODES);
    __syncthreads();
    if (tid < D_OUT) {
        float v = 0.f;
        for (int k = 0; k < D2; k++) v += shp[k] * Wf[k * D_OUT + tid];
        shv[tid] = v + bf[tid];
    }
    __syncthreads();
    if (tid == 0) {
        float m = 0.f;
        for (int k = 0; k < D_OUT; k++) m += shv[k];
        m /= (float)D_OUT;
        float va = 0.f;
        for (int k = 0; k < D_OUT; k++) { float d = shv[k] - m; va += d * d; }
        va /= (float)D_OUT;
        smu  = m;
        sinv = 1.f / sqrtf(va + 1e-5f);  // final LN: /sqrt(var+eps)
    }
    __syncthreads();
    if (tid < D_OUT) {
        float y = (shv[tid] - smu) * sinv * gx[tid] + bx[tid];
        out[tid] = fmaxf(y, 0.f);
    }
}

// ---------------- launch ------------------------------------------------------
extern "C" void kernel_launch(void* const* d_in, const int* in_sizes, int n_in,
                              void* d_out, int out_size) {
    const float* x   = (const float*)d_in[0];
    const int*   ei  = (const int*)d_in[1];     // int32! (JAX x64 disabled)
    const float* t1  = (const float*)d_in[2];
    const float* Wl1 = (const float*)d_in[3];
    const float* bl1 = (const float*)d_in[4];
    const float* Wr1 = (const float*)d_in[5];
    const float* g1  = (const float*)d_in[6];
    const float* be1 = (const float*)d_in[7];
    const float* t2  = (const float*)d_in[8];
    const float* Wl2 = (const float*)d_in[9];
    const float* bl2 = (const float*)d_in[10];
    const float* Wr2 = (const float*)d_in[11];
    const float* g2  = (const float*)d_in[12];
    const float* be2 = (const float*)d_in[13];
    const float* Wf  = (const float*)d_in[14];
    const float* bf  = (const float*)d_in[15];
    const float* gx  = (const float*)d_in[16];
    const float* bx  = (const float*)d_in[17];
    float*       out = (float*)d_out;

    zero_k<<<(NNODES + 255) / 256, 256>>>();
    hist_k<<<(NEDGES + 255) / 256, 256>>>(ei);
    scan_k<<<1, 1024>>>();
    scatter_k<<<(NEDGES + 255) / 256, 256>>>(ei);

    // ---- layer 1 ----
    agg_k<D_IN><<<NNODES, D_IN>>>(x, t1);
    gemm_dual_k<<<dim3(D1 / 128, (NNODES + 127) / 128), 256>>>(
        x, Wl1, Wr1, bl1, D_IN, NNODES, D1);
    stats_k<<<NSTAT, 256>>>((size_t)NNODES * D1);
    fin_k<<<1, 1024>>>((size_t)NNODES * D1);
    lnrelu_k<<<2048, 256>>>(g1, be1, 1, D1 - 1, (size_t)NNODES * D1);

    // ---- layer 2 ----
    agg_k<D1><<<NNODES, D1>>>(nullptr, t2);
    gemm_dual_k<<<dim3(D2 / 128, (NNODES + 127) / 128), 256>>>(
        nullptr, Wl2, Wr2, bl2, D1, NNODES, D2);
    stats_k<<<NSTAT, 256>>>((size_t)NNODES * D2);
    fin_k<<<1, 1024>>>((size_t)NNODES * D2);
    lnrelu_k<<<2048, 256>>>(g2, be2, 2, D2 - 1, (size_t)NNODES * D2);

    // ---- head ----
    colsum_k<<<NPSUM, 256>>>();
    final_k<<<1, D2>>>(Wf, bf, gx, bx, out);
}

// round 17
// speedup vs baseline: 1.0077x; 1.0033x over previous
#include <cuda_runtime.h>
#include <math.h>

#define NNODES 20000
#define NEDGES 320000
#define D_IN   256
#define D1     512
#define D2     256
#define D_OUT  64
#define NSTAT  1024   // stats partial blocks
#define NPSUM  128    // colsum partial blocks

// ---------------- scratch (device globals; referenced directly by kernels) --
__device__ int    g_deg[NNODES];
__device__ int    g_rowptr[NNODES + 1];
__device__ int    g_cursor[NNODES];
__device__ int    g_col[NEDGES];
__device__ float  g_agg[NNODES * D1];    // aggregation output / reused as hn2
__device__ float  g_h[NNODES * D1];      // GEMM output
__device__ float  g_hn[NNODES * D1];     // normalized+relu features (layer1)
__device__ float2 g_part[NSTAT];         // stats partials {sum, sumsq}
__device__ float2 g_muinv;               // finalized {mu, 1/(std+eps)}
__device__ float  g_psum[NPSUM * D2];    // column-sum partials

// ---------------- setup: zero per-replay state ------------------------------
__global__ void zero_k() {
    int i = blockIdx.x * blockDim.x + threadIdx.x;
    if (i < NNODES) { g_deg[i] = 0; g_cursor[i] = 0; }
}

// ---------------- CSR build (edge_index is INT32: [2, E] row-major) ---------
__global__ void hist_k(const int* __restrict__ ei) {
    int i = blockIdx.x * blockDim.x + threadIdx.x;
    if (i < NEDGES) {
        int d = ei[NEDGES + i];
        if ((unsigned)d < (unsigned)NNODES) atomicAdd(&g_deg[d], 1);
    }
}

__global__ void scan_k() {  // single-block exclusive scan over g_deg
    __shared__ int sh[1024];
    __shared__ int carry;
    if (threadIdx.x == 0) carry = 0;
    __syncthreads();
    for (int base = 0; base < NNODES; base += 1024) {
        int i = base + (int)threadIdx.x;
        int v = (i < NNODES) ? g_deg[i] : 0;
        sh[threadIdx.x] = v;
        __syncthreads();
        for (int off = 1; off < 1024; off <<= 1) {
            int t = (threadIdx.x >= (unsigned)off) ? sh[threadIdx.x - off] : 0;
            __syncthreads();
            sh[threadIdx.x] += t;
            __syncthreads();
        }
        if (i < NNODES) g_rowptr[i] = carry + sh[threadIdx.x] - v;
        __syncthreads();
        if (threadIdx.x == 0) carry += sh[1023];
        __syncthreads();
    }
    if (threadIdx.x == 0) g_rowptr[NNODES] = carry;
}

__global__ void scatter_k(const int* __restrict__ ei) {
    int i = blockIdx.x * blockDim.x + threadIdx.x;
    if (i < NEDGES) {
        int s = ei[i];
        int d = ei[NEDGES + i];
        if ((unsigned)s < (unsigned)NNODES && (unsigned)d < (unsigned)NNODES) {
            int pos = atomicAdd(&g_cursor[d], 1);
            g_col[g_rowptr[d] + pos] = s;
        }
    }
}

// ---------------- softmax aggregation (online, one pass) --------------------
// Fx == nullptr -> read features from g_hn. Output always g_agg.
template <int D>
__global__ void agg_k(const float* __restrict__ Fx, const float* __restrict__ t) {
    const float* F = Fx ? Fx : (const float*)g_hn;
    int row = blockIdx.x;
    int c   = threadIdx.x;
    int s0 = g_rowptr[row], s1 = g_rowptr[row + 1];
    float tc  = t[c];
    float mx  = -3.0e38f, den = 0.f, num = 0.f;
    for (int e = s0; e < s1; e++) {
        int   s = g_col[e];
        float m = F[(size_t)s * D + c];
        float a = m * tc;
        if (a > mx) {
            float r = __expf(mx - a);
            den *= r; num *= r; mx = a;
        }
        float w = __expf(a - mx);
        den += w;
        num += m * w;
    }
    g_agg[(size_t)row * D + c] = (s1 > s0) ? (num / den) : 0.f;
}

// ---------------- fused dual GEMM: g_h = g_agg@W1 + A2@W2 + bias ------------
// A2x == nullptr -> A2 = g_hn. 128x128 tile, BK=8, 256 threads, 8x8/thread.
__global__ void __launch_bounds__(256, 2) gemm_dual_k(
    const float* __restrict__ A2x, const float* __restrict__ W1,
    const float* __restrict__ W2, const float* __restrict__ bias,
    int K, int M, int Nn)
{
    __shared__ float As[8][132];
    __shared__ float Bs[8][132];
    const float* A2 = A2x ? A2x : (const float*)g_hn;
    const int tid     = threadIdx.x;
    const int rowBase = blockIdx.y * 128;
    const int colBase = blockIdx.x * 128;
    const int aRow = tid >> 1;
    const int aCol = (tid & 1) << 2;
    const int bRow = tid >> 5;
    const int bCol = (tid & 31) << 2;
    const int ty = tid >> 4;
    const int tx = tid & 15;

    float acc[8][8];
#pragma unroll
    for (int i = 0; i < 8; i++)
#pragma unroll
        for (int j = 0; j < 8; j++) acc[i][j] = 0.f;

    for (int part = 0; part < 2; part++) {
        const float* A = part ? A2 : (const float*)g_agg;
        const float* W = part ? W2 : W1;
        for (int k0 = 0; k0 < K; k0 += 8) {
            float4 av = make_float4(0.f, 0.f, 0.f, 0.f);
            int ar = rowBase + aRow;
            if (ar < M)
                av = *reinterpret_cast<const float4*>(&A[(size_t)ar * K + k0 + aCol]);
            As[aCol + 0][aRow] = av.x;
            As[aCol + 1][aRow] = av.y;
            As[aCol + 2][aRow] = av.z;
            As[aCol + 3][aRow] = av.w;
            *reinterpret_cast<float4*>(&Bs[bRow][bCol]) =
                *reinterpret_cast<const float4*>(&W[(size_t)(k0 + bRow) * Nn + colBase + bCol]);
            __syncthreads();
#pragma unroll
            for (int k = 0; k < 8; k++) {
                float a[8], b[8];
                *reinterpret_cast<float4*>(a)     = *reinterpret_cast<float4*>(&As[k][ty * 8]);
                *reinterpret_cast<float4*>(a + 4) = *reinterpret_cast<float4*>(&As[k][ty * 8 + 4]);
                *reinterpret_cast<float4*>(b)     = *reinterpret_cast<float4*>(&Bs[k][tx * 8]);
                *reinterpret_cast<float4*>(b + 4) = *reinterpret_cast<float4*>(&Bs[k][tx * 8 + 4]);
#pragma unroll
                for (int i = 0; i < 8; i++)
#pragma unroll
                    for (int j = 0; j < 8; j++) acc[i][j] += a[i] * b[j];
            }
            __syncthreads();
        }
    }

#pragma unroll
    for (int i = 0; i < 8; i++) {
        int r = rowBase + ty * 8 + i;
        if (r < M) {
            int cc = colBase + tx * 8;
#pragma unroll
            for (int j = 0; j < 8; j++)
                g_h[(size_t)r * Nn + cc + j] = acc[i][j] + bias[cc + j];
        }
    }
}

// ---------------- graph-LN statistics (2-stage, no 64-bit atomics) ----------
__global__ void stats_k(size_t n) {  // grid = NSTAT blocks, 256 threads
    float s = 0.f, ss = 0.f;
    for (size_t i = (size_t)blockIdx.x * blockDim.x + threadIdx.x; i < n;
         i += (size_t)gridDim.x * blockDim.x) {
        float v = g_h[i];
        s += v;
        ss += v * v;
    }
    for (int o = 16; o; o >>= 1) {
        s  += __shfl_down_sync(0xffffffffu, s, o);
        ss += __shfl_down_sync(0xffffffffu, ss, o);
    }
    __shared__ float ws[2][8];
    int w = threadIdx.x >> 5, l = threadIdx.x & 31;
    if (l == 0) { ws[0][w] = s; ws[1][w] = ss; }
    __syncthreads();
    if (threadIdx.x == 0) {
        float ts = 0.f, tss = 0.f;
        for (int i = 0; i < 8; i++) { ts += ws[0][i]; tss += ws[1][i]; }
        g_part[blockIdx.x] = make_float2(ts, tss);
    }
}

__global__ void fin_k(size_t n) {  // single block, 1024 threads
    __shared__ double ds[1024], dss[1024];
    float2 p = g_part[threadIdx.x];
    ds[threadIdx.x]  = (double)p.x;
    dss[threadIdx.x] = (double)p.y;
    __syncthreads();
    for (int o = 512; o; o >>= 1) {
        if ((int)threadIdx.x < o) {
            ds[threadIdx.x]  += ds[threadIdx.x + o];
            dss[threadIdx.x] += dss[threadIdx.x + o];
        }
        __syncthreads();
    }
    if (threadIdx.x == 0) {
        double mu  = ds[0] / (double)n;
        double var = dss[0] / (double)n - mu * mu;
        if (var < 0.0) var = 0.0;
        double inv = 1.0 / (sqrt(var) + 1e-5);  // graph-LN: (x-mu)/(std+eps)
        g_muinv = make_float2((float)mu, (float)inv);
    }
}

// layer==1 -> out g_hn ; layer==2 -> out g_agg (reused)
__global__ void lnrelu_k(const float* __restrict__ g, const float* __restrict__ b,
                         int layer, int Dmask, size_t n) {
    float* out = (layer == 1) ? g_hn : g_agg;
    float2 mi = g_muinv;
    for (size_t i = (size_t)blockIdx.x * blockDim.x + threadIdx.x; i < n;
         i += (size_t)gridDim.x * blockDim.x) {
        int   c = (int)(i & (size_t)Dmask);
        float y = (g_h[i] - mi.x) * mi.y * g[c] + b[c];
        out[i] = fmaxf(y, 0.f);
    }
}

// ---------------- pooling + head (deterministic, no atomics) ----------------
__global__ void colsum_k() {  // grid = NPSUM blocks x 256 threads, reads g_agg
    int c = threadIdx.x;
    float s = 0.f;
    for (int r = blockIdx.x; r < NNODES; r += gridDim.x)
        s += g_agg[(size_t)r * D2 + c];
    g_psum[blockIdx.x * D2 + c] = s;
}

__global__ void final_k(const float* __restrict__ Wf, const float* __restrict__ bf,
                        const float* __restrict__ gx, const float* __restrict__ bx,
                        float* __restrict__ out) {
    __shared__ float shp[D2];
    __shared__ float shv[D_OUT];
    __shared__ float smu, sinv;
    int tid = threadIdx.x;  // 256
    float s = 0.f;
    for (int p = 0; p < NPSUM; p++) s += g_psum[p * D2 + tid];
    shp[tid] = s * (1.f / (float)NNODES);
    __syncthreads();
    if (tid < D_OUT) {
        float v = 0.f;
        for (int k = 0; k < D2; k++) v += shp[k] * Wf[k * D_OUT + tid];
        shv[tid] = v + bf[tid];
    }
    __syncthreads();
    if (tid == 0) {
        float m = 0.f;
        for (int k = 0; k < D_OUT; k++) m += shv[k];
        m /= (float)D_OUT;
        float va = 0.f;
        for (int k = 0; k < D_OUT; k++) { float d = shv[k] - m; va += d * d; }
        va /= (float)D_OUT;
        smu  = m;
        sinv = 1.f / sqrtf(va + 1e-5f);  // final LN: /sqrt(var+eps)
    }
    __syncthreads();
    if (tid < D_OUT) {
        float y = (shv[tid] - smu) * sinv * gx[tid] + bx[tid];
        out[tid] = fmaxf(y, 0.f);
    }
}

// ---------------- launch ------------------------------------------------------
extern "C" void kernel_launch(void* const* d_in, const int* in_sizes, int n_in,
                              void* d_out, int out_size) {
    const float* x   = (const float*)d_in[0];
    const int*   ei  = (const int*)d_in[1];     // int32! (JAX x64 disabled)
    const float* t1  = (const float*)d_in[2];
    const float* Wl1 = (const float*)d_in[3];
    const float* bl1 = (const float*)d_in[4];
    const float* Wr1 = (const float*)d_in[5];
    const float* g1  = (const float*)d_in[6];
    const float* be1 = (const float*)d_in[7];
    const float* t2  = (const float*)d_in[8];
    const float* Wl2 = (const float*)d_in[9];
    const float* bl2 = (const float*)d_in[10];
    const float* Wr2 = (const float*)d_in[11];
    const float* g2  = (const float*)d_in[12];
    const float* be2 = (const float*)d_in[13];
    const float* Wf  = (const float*)d_in[14];
    const float* bf  = (const float*)d_in[15];
    const float* gx  = (const float*)d_in[16];
    const float* bx  = (const float*)d_in[17];
    float*       out = (float*)d_out;

    zero_k<<<(NNODES + 255) / 256, 256>>>();
    hist_k<<<(NEDGES + 255) / 256, 256>>>(ei);
    scan_k<<<1, 1024>>>();
    scatter_k<<<(NEDGES + 255) / 256, 256>>>(ei);

    // ---- layer 1 ----
    agg_k<D_IN><<<NNODES, D_IN>>>(x, t1);
    gemm_dual_k<<<dim3(D1 / 128, (NNODES + 127) / 128), 256>>>(
        x, Wl1, Wr1, bl1, D_IN, NNODES, D1);
    stats_k<<<NSTAT, 256>>>((size_t)NNODES * D1);
    fin_k<<<1, 1024>>>((size_t)NNODES * D1);
    lnrelu_k<<<2048, 256>>>(g1, be1, 1, D1 - 1, (size_t)NNODES * D1);

    // ---- layer 2 ----
    agg_k<D1><<<NNODES, D1>>>(nullptr, t2);
    gemm_dual_k<<<dim3(D2 / 128, (NNODES + 127) / 128), 256>>>(
        nullptr, Wl2, Wr2, bl2, D1, NNODES, D2);
    stats_k<<<NSTAT, 256>>>((size_t)NNODES * D2);
    fin_k<<<1, 1024>>>((size_t)NNODES * D2);
    lnrelu_k<<<2048, 256>>>(g2, be2, 2, D2 - 1, (size_t)NNODES * D2);

    // ---- head ----
    colsum_k<<<NPSUM, 256>>>();
    final_k<<<1, D2>>>(Wf, bf, gx, bx, out);
}